// round 5
// baseline (speedup 1.0000x reference)
#include <cuda_runtime.h>
#include <cuda_bf16.h>
#include <math.h>
#include <stdint.h>

// Problem constants
constexpr int NN = 8192;
constexpr int DD = 1024;
constexpr float BD = 819.2f;   // 0.1 * n
constexpr float BU = 7372.8f;  // 0.9 * n

// ---------------- device scratch (static, allocation-free) ----------------
__device__ __nv_bfloat16 g_P0[(size_t)NN * NN];  // 128 MB, P0 = exp(L - 1)
__device__ __nv_bfloat16 g_Abf[(size_t)NN * DD]; // 16 MB
__device__ __nv_bfloat16 g_Bbf[(size_t)NN * DD]; // 16 MB
__device__ float g_c[NN], g_c2[NN];
__device__ float g_r[NN], g_r2[NN];
__device__ float g_u[NN], g_u2[NN];   // row sums; reused as CE S_img/S_txt accumulators
__device__ float g_s[NN], g_s2[NN];   // col sums
__device__ float g_diag[NN], g_diag2[NN];
__device__ float g_sums[1];

// ---------------- init ----------------
__global__ void init_kernel() {
    int i = blockIdx.x * blockDim.x + threadIdx.x;
    if (i < NN) {
        g_c[i] = 1.0f; g_c2[i] = 1.0f;
        g_u[i] = 0.0f; g_u2[i] = 0.0f;
        g_s[i] = 0.0f; g_s2[i] = 0.0f;
    }
    if (i == 0) g_sums[0] = 0.0f;
}

// ---------------- fp32 -> bf16 convert (vectorized) ----------------
__global__ __launch_bounds__(256) void convert_kernel(
    const float* __restrict__ A, const float* __restrict__ B) {
    int i = blockIdx.x * blockDim.x + threadIdx.x;  // float4 index
    const int n4 = NN * DD / 4;
    if (i < n4) {
        float4 va = reinterpret_cast<const float4*>(A)[i];
        __nv_bfloat162 a0 = __floats2bfloat162_rn(va.x, va.y);
        __nv_bfloat162 a1 = __floats2bfloat162_rn(va.z, va.w);
        reinterpret_cast<uint2*>(g_Abf)[i] =
            make_uint2(*reinterpret_cast<uint32_t*>(&a0),
                       *reinterpret_cast<uint32_t*>(&a1));
        float4 vb = reinterpret_cast<const float4*>(B)[i];
        __nv_bfloat162 b0 = __floats2bfloat162_rn(vb.x, vb.y);
        __nv_bfloat162 b1 = __floats2bfloat162_rn(vb.z, vb.w);
        reinterpret_cast<uint2*>(g_Bbf)[i] =
            make_uint2(*reinterpret_cast<uint32_t*>(&b0),
                       *reinterpret_cast<uint32_t*>(&b1));
    }
}

// ---------------- tensor-core GEMM (mma.sync): P0 = bf16(exp(A @ B^T - 1)) ----
// BM=BN=128, BK=64, 256 threads (8 warps: 2 m x 4 n), cp.async double buffer,
// SW128 swizzled smem, ldmatrix + mma.sync m16n8k16 bf16 -> fp32.
constexpr int BK = 64;
constexpr int KT = DD / BK;                // 16
constexpr int STAGE_BYTES = 2 * 128 * BK * 2;  // A tile + B tile = 32KB
constexpr int B_OFF = 128 * BK * 2;            // 16KB into stage

__device__ __forceinline__ void cp_async16(uint32_t s, const void* g) {
    asm volatile("cp.async.cg.shared.global [%0], [%1], 16;\n" :: "r"(s), "l"(g));
}
__device__ __forceinline__ void cp_commit() {
    asm volatile("cp.async.commit_group;\n");
}
template <int N>
__device__ __forceinline__ void cp_wait() {
    asm volatile("cp.async.wait_group %0;\n" :: "n"(N));
}
__device__ __forceinline__ void ldsm4(uint32_t& r0, uint32_t& r1, uint32_t& r2,
                                      uint32_t& r3, uint32_t addr) {
    asm volatile("ldmatrix.sync.aligned.m8n8.x4.shared.b16 {%0,%1,%2,%3}, [%4];\n"
                 : "=r"(r0), "=r"(r1), "=r"(r2), "=r"(r3) : "r"(addr));
}
__device__ __forceinline__ void mma16816(float* c, const uint32_t* a,
                                         const uint32_t* b) {
    asm volatile(
        "mma.sync.aligned.m16n8k16.row.col.f32.bf16.bf16.f32 "
        "{%0,%1,%2,%3}, {%4,%5,%6,%7}, {%8,%9}, {%0,%1,%2,%3};\n"
        : "+f"(c[0]), "+f"(c[1]), "+f"(c[2]), "+f"(c[3])
        : "r"(a[0]), "r"(a[1]), "r"(a[2]), "r"(a[3]), "r"(b[0]), "r"(b[1]));
}

__global__ __launch_bounds__(256) void gemm_bf16_exp_kernel() {
    extern __shared__ char smem[];
    const uint32_t sbase = (uint32_t)__cvta_generic_to_shared(smem);
    const int tid = threadIdx.x;
    const int wid = tid >> 5;
    const int lane = tid & 31;
    const int warp_m = wid & 1;   // 0..1, 64 rows each
    const int warp_n = wid >> 1;  // 0..3, 32 cols each
    const int bi = blockIdx.y * 128;
    const int bj = blockIdx.x * 128;

    float acc[4][4][4];
#pragma unroll
    for (int mt = 0; mt < 4; mt++)
#pragma unroll
        for (int nt = 0; nt < 4; nt++)
#pragma unroll
            for (int r = 0; r < 4; r++) acc[mt][nt][r] = 0.0f;

    auto load_stage = [&](int kt, int stage) {
        const int k0 = kt * BK;
        const uint32_t so = sbase + stage * STAGE_BYTES;
#pragma unroll
        for (int i = 0; i < 4; i++) {
            int u = tid + i * 256;
            int row = u >> 3;
            int chunk = u & 7;
            uint32_t d = so + row * 128 + ((chunk * 16) ^ ((row & 7) << 4));
            cp_async16(d, &g_Abf[(size_t)(bi + row) * DD + k0 + chunk * 8]);
            cp_async16(d + B_OFF, &g_Bbf[(size_t)(bj + row) * DD + k0 + chunk * 8]);
        }
        cp_commit();
    };

    load_stage(0, 0);

    for (int kt = 0; kt < KT; kt++) {
        const int stage = kt & 1;
        if (kt + 1 < KT) {
            load_stage(kt + 1, stage ^ 1);
            cp_wait<1>();
        } else {
            cp_wait<0>();
        }
        __syncthreads();

        const uint32_t sa = sbase + stage * STAGE_BYTES;
        const uint32_t sb = sa + B_OFF;
#pragma unroll
        for (int kk = 0; kk < BK / 16; kk++) {
            uint32_t a[4][4];
#pragma unroll
            for (int mt = 0; mt < 4; mt++) {
                int row = warp_m * 64 + mt * 16 + (lane & 15);
                int chunk = kk * 2 + (lane >> 4);
                uint32_t addr = sa + row * 128 + ((chunk * 16) ^ ((row & 7) << 4));
                ldsm4(a[mt][0], a[mt][1], a[mt][2], a[mt][3], addr);
            }
            uint32_t b[2][4];
#pragma unroll
            for (int pair = 0; pair < 2; pair++) {
                int rown = warp_n * 32 + pair * 16 + ((lane >> 4) << 3) + (lane & 7);
                int chunk = kk * 2 + ((lane >> 3) & 1);
                uint32_t addr = sb + rown * 128 + ((chunk * 16) ^ ((rown & 7) << 4));
                ldsm4(b[pair][0], b[pair][1], b[pair][2], b[pair][3], addr);
            }
#pragma unroll
            for (int mt = 0; mt < 4; mt++)
#pragma unroll
                for (int nt = 0; nt < 4; nt++)
                    mma16816(acc[mt][nt], a[mt], &b[nt >> 1][(nt & 1) * 2]);
        }
        __syncthreads();
    }

    // Epilogue: exp(x - 1) -> bf16, direct global stores (bf16x2 per reg pair)
    const int lrow = lane >> 2;
    const int lcol = (lane & 3) * 2;
#pragma unroll
    for (int mt = 0; mt < 4; mt++) {
#pragma unroll
        for (int nt = 0; nt < 4; nt++) {
            int gi0 = bi + warp_m * 64 + mt * 16 + lrow;
            int gj = bj + warp_n * 32 + nt * 8 + lcol;
            __nv_bfloat162 v0 = __floats2bfloat162_rn(
                __expf(acc[mt][nt][0] - 1.0f), __expf(acc[mt][nt][1] - 1.0f));
            __nv_bfloat162 v1 = __floats2bfloat162_rn(
                __expf(acc[mt][nt][2] - 1.0f), __expf(acc[mt][nt][3] - 1.0f));
            *reinterpret_cast<__nv_bfloat162*>(&g_P0[(size_t)gi0 * NN + gj]) = v0;
            *reinterpret_cast<__nv_bfloat162*>(&g_P0[(size_t)(gi0 + 8) * NN + gj]) = v1;
        }
    }
}

// ---------------- fused dual matvec (uint4 loads, 4-row ILP, 32-row blocks) ----
// out_row[i] += sum_j P0[i][j] * f(a[j]);  out_col[j] += sum_i P0[i][j] * f(b[i])
// f(x) = 1/x when RECIP else x. grid = (4, 256): 1024 blocks for occupancy.
template <bool RECIP>
__global__ __launch_bounds__(256) void dual_matvec_kernel(
    const float* __restrict__ a, const float* __restrict__ b,
    float* __restrict__ out_row, float* __restrict__ out_col) {
    const int ROWS = 32;
    const int tid = threadIdx.x;
    const int j = (blockIdx.x * 256 + tid) * 8;
    const int i0 = blockIdx.y * ROWS;
    __shared__ float bsh[ROWS];
    __shared__ float rowpart[ROWS][9];
    if (tid < ROWS) {
        float v = b[i0 + tid];
        bsh[tid] = RECIP ? 1.0f / v : v;
    }
    __syncthreads();

    float av[8];
    {
        float4 a0 = *reinterpret_cast<const float4*>(&a[j]);
        float4 a1 = *reinterpret_cast<const float4*>(&a[j + 4]);
        av[0] = a0.x; av[1] = a0.y; av[2] = a0.z; av[3] = a0.w;
        av[4] = a1.x; av[5] = a1.y; av[6] = a1.z; av[7] = a1.w;
        if (RECIP)
#pragma unroll
            for (int k = 0; k < 8; k++) av[k] = 1.0f / av[k];
    }
    float colacc[8];
#pragma unroll
    for (int k = 0; k < 8; k++) colacc[k] = 0.0f;
    const int warp = tid >> 5, lane = tid & 31;
    const __nv_bfloat16* base = g_P0 + (size_t)i0 * NN + j;

    for (int ii = 0; ii < ROWS; ii += 4) {
        // 4 independent row loads (MLP=4)
        uint4 u[4];
#pragma unroll
        for (int r = 0; r < 4; r++)
            u[r] = *reinterpret_cast<const uint4*>(base + (size_t)(ii + r) * NN);
        float dots[4];
#pragma unroll
        for (int r = 0; r < 4; r++) {
            float v[8];
            float2 f;
            f = __bfloat1622float2(*reinterpret_cast<__nv_bfloat162*>(&u[r].x));
            v[0] = f.x; v[1] = f.y;
            f = __bfloat1622float2(*reinterpret_cast<__nv_bfloat162*>(&u[r].y));
            v[2] = f.x; v[3] = f.y;
            f = __bfloat1622float2(*reinterpret_cast<__nv_bfloat162*>(&u[r].z));
            v[4] = f.x; v[5] = f.y;
            f = __bfloat1622float2(*reinterpret_cast<__nv_bfloat162*>(&u[r].w));
            v[6] = f.x; v[7] = f.y;
            float bi = bsh[ii + r];
            float dot = 0.0f;
#pragma unroll
            for (int k = 0; k < 8; k++) {
                colacc[k] = fmaf(v[k], bi, colacc[k]);
                dot = fmaf(v[k], av[k], dot);
            }
            dots[r] = dot;
        }
        // 4 interleaved shfl reduction chains (hides SHFL latency)
#pragma unroll
        for (int o = 16; o > 0; o >>= 1) {
#pragma unroll
            for (int r = 0; r < 4; r++)
                dots[r] += __shfl_down_sync(0xffffffffu, dots[r], o);
        }
        if (lane == 0) {
#pragma unroll
            for (int r = 0; r < 4; r++) rowpart[ii + r][warp] = dots[r];
        }
    }
    __syncthreads();
    if (tid < ROWS) {
        float sacc = 0.f;
#pragma unroll
        for (int w = 0; w < 8; w++) sacc += rowpart[tid][w];
        atomicAdd(&out_row[i0 + tid], sacc);
    }
#pragma unroll
    for (int k = 0; k < 8; k++) atomicAdd(&out_col[j + k], colacc[k]);
}

// colupd: r = 1/u (persists for CE), c/c2 two-step update from s/s2,
// then zero u,u2,s,s2 for the next iteration / CE accumulators.
__global__ void colupd_kernel() {
    int i = blockIdx.x * blockDim.x + threadIdx.x;
    if (i < NN) {
        g_r[i] = 1.0f / g_u[i];
        g_r2[i] = 1.0f / g_u2[i];
        float cv = g_c[i], sv = g_s[i];
        cv *= fmaxf(BD / (cv * sv), 1.0f);
        cv *= fminf(BU / (cv * sv), 1.0f);
        g_c[i] = cv;
        float cv2 = g_c2[i], sv2 = g_s2[i];
        cv2 *= fmaxf(BD / (cv2 * sv2), 1.0f);
        cv2 *= fminf(BU / (cv2 * sv2), 1.0f);
        g_c2[i] = cv2;
        g_u[i] = 0.0f; g_u2[i] = 0.0f;
        g_s[i] = 0.0f; g_s2[i] = 0.0f;
    }
}

// ---------------- fused CE: both directions in ONE read of P0 ----------------
// Image: S_img[i] = sum_j exp(r_i * P0_ij * c_j)      -> atomic into g_u
// Text:  S_txt[j] = sum_i exp(r2_j * P0_ij * c2_i)    -> atomic into g_u2
// diag:  g_diag[i] = r_i P0[i][lab_i] c[lab_i];  g_diag2[j] = r2_j P0[lab_j][j] c2[lab_j]
__global__ __launch_bounds__(256) void ce_fused_kernel(const int* __restrict__ labels) {
    const int ROWS = 32;
    const int tid = threadIdx.x;
    const int j = (blockIdx.x * 256 + tid) * 8;
    const int i0 = blockIdx.y * ROWS;
    __shared__ float rsh[ROWS], c2sh[ROWS];
    __shared__ int labsh[ROWS];
    __shared__ float rowpart[ROWS][9];
    if (tid < ROWS) {
        rsh[tid] = g_r[i0 + tid];
        c2sh[tid] = g_c2[i0 + tid];
        labsh[tid] = labels[i0 + tid];
    }
    __syncthreads();

    float cj[8], r2j[8];
    int labc[8];
    {
        float4 t0 = *reinterpret_cast<const float4*>(&g_c[j]);
        float4 t1 = *reinterpret_cast<const float4*>(&g_c[j + 4]);
        cj[0] = t0.x; cj[1] = t0.y; cj[2] = t0.z; cj[3] = t0.w;
        cj[4] = t1.x; cj[5] = t1.y; cj[6] = t1.z; cj[7] = t1.w;
        t0 = *reinterpret_cast<const float4*>(&g_r2[j]);
        t1 = *reinterpret_cast<const float4*>(&g_r2[j + 4]);
        r2j[0] = t0.x; r2j[1] = t0.y; r2j[2] = t0.z; r2j[3] = t0.w;
        r2j[4] = t1.x; r2j[5] = t1.y; r2j[6] = t1.z; r2j[7] = t1.w;
        int4 l0 = *reinterpret_cast<const int4*>(&labels[j]);
        int4 l1 = *reinterpret_cast<const int4*>(&labels[j + 4]);
        labc[0] = l0.x; labc[1] = l0.y; labc[2] = l0.z; labc[3] = l0.w;
        labc[4] = l1.x; labc[5] = l1.y; labc[6] = l1.z; labc[7] = l1.w;
    }
    float colacc[8];
#pragma unroll
    for (int k = 0; k < 8; k++) colacc[k] = 0.0f;
    const int warp = tid >> 5, lane = tid & 31;
    const __nv_bfloat16* base = g_P0 + (size_t)i0 * NN + j;

    for (int ii = 0; ii < ROWS; ii += 2) {
        uint4 u[2];
#pragma unroll
        for (int r = 0; r < 2; r++)
            u[r] = *reinterpret_cast<const uint4*>(base + (size_t)(ii + r) * NN);
        float dots[2];
#pragma unroll
        for (int r = 0; r < 2; r++) {
            float v[8];
            float2 f;
            f = __bfloat1622float2(*reinterpret_cast<__nv_bfloat162*>(&u[r].x));
            v[0] = f.x; v[1] = f.y;
            f = __bfloat1622float2(*reinterpret_cast<__nv_bfloat162*>(&u[r].y));
            v[2] = f.x; v[3] = f.y;
            f = __bfloat1622float2(*reinterpret_cast<__nv_bfloat162*>(&u[r].z));
            v[4] = f.x; v[5] = f.y;
            f = __bfloat1622float2(*reinterpret_cast<__nv_bfloat162*>(&u[r].w));
            v[6] = f.x; v[7] = f.y;
            const int irow = i0 + ii + r;
            const float ri = rsh[ii + r], c2i = c2sh[ii + r];
            const int labr = labsh[ii + r];
            float rdot = 0.0f;
#pragma unroll
            for (int k = 0; k < 8; k++) {
                float e1 = ri * v[k] * cj[k];
                float e2 = r2j[k] * v[k] * c2i;
                rdot += __expf(e1);
                colacc[k] += __expf(e2);
                if (j + k == labr) g_diag[irow] = e1;
                if (irow == labc[k]) g_diag2[j + k] = e2;
            }
            dots[r] = rdot;
        }
#pragma unroll
        for (int o = 16; o > 0; o >>= 1) {
#pragma unroll
            for (int r = 0; r < 2; r++)
                dots[r] += __shfl_down_sync(0xffffffffu, dots[r], o);
        }
        if (lane == 0) {
#pragma unroll
            for (int r = 0; r < 2; r++) rowpart[ii + r][warp] = dots[r];
        }
    }
    __syncthreads();
    if (tid < ROWS) {
        float sacc = 0.f;
#pragma unroll
        for (int w = 0; w < 8; w++) sacc += rowpart[tid][w];
        atomicAdd(&g_u[i0 + tid], sacc);
    }
#pragma unroll
    for (int k = 0; k < 8; k++) atomicAdd(&g_u2[j + k], colacc[k]);
}

__global__ __launch_bounds__(256) void ce_reduce_kernel() {
    int t = blockIdx.x * 256 + threadIdx.x;
    float v = (logf(g_u[t]) - g_diag[t]) + (logf(g_u2[t]) - g_diag2[t]);
    __shared__ float wsum[8];
#pragma unroll
    for (int o = 16; o > 0; o >>= 1)
        v += __shfl_down_sync(0xffffffffu, v, o);
    int warp = threadIdx.x >> 5, lane = threadIdx.x & 31;
    if (lane == 0) wsum[warp] = v;
    __syncthreads();
    if (threadIdx.x == 0) {
        float tt = 0.f;
#pragma unroll
        for (int w = 0; w < 8; w++) tt += wsum[w];
        atomicAdd(&g_sums[0], tt);
    }
}

__global__ void finalize_kernel(float* __restrict__ out) {
    out[0] = g_sums[0] / (2.0f * (float)NN);
}

// ---------------- launch ----------------
extern "C" void kernel_launch(void* const* d_in, const int* in_sizes, int n_in,
                              void* d_out, int out_size) {
    const float* A = (const float*)d_in[0];   // all_image_features [N, D]
    const float* B = (const float*)d_in[1];   // all_text_features  [N, D]
    const int* labels = (const int*)d_in[3];
    float* out = (float*)d_out;

    float *c, *c2, *u, *u2, *s, *s2;
    cudaGetSymbolAddress((void**)&c, g_c);
    cudaGetSymbolAddress((void**)&c2, g_c2);
    cudaGetSymbolAddress((void**)&u, g_u);
    cudaGetSymbolAddress((void**)&u2, g_u2);
    cudaGetSymbolAddress((void**)&s, g_s);
    cudaGetSymbolAddress((void**)&s2, g_s2);

    cudaFuncSetAttribute(gemm_bf16_exp_kernel,
                         cudaFuncAttributeMaxDynamicSharedMemorySize,
                         2 * STAGE_BYTES);

    init_kernel<<<NN / 256, 256>>>();
    convert_kernel<<<NN * DD / 4 / 256, 256>>>(A, B);
    gemm_bf16_exp_kernel<<<dim3(64, 64), 256, 2 * STAGE_BYTES>>>();

    for (int it = 0; it < 5; it++) {
        // pass1: u_i += sum_j P0_ij c_j ; u2_j += sum_i P0_ij c2_i
        dual_matvec_kernel<false><<<dim3(4, 256), 256>>>(c, c2, u, u2);
        // pass2: s2_i += sum_j P0_ij (1/u2_j) ; s_j += sum_i P0_ij (1/u_i)
        dual_matvec_kernel<true><<<dim3(4, 256), 256>>>(u2, u, s2, s);
        colupd_kernel<<<NN / 256, 256>>>();
    }

    ce_fused_kernel<<<dim3(4, 256), 256>>>(labels);
    ce_reduce_kernel<<<NN / 256, 256>>>();
    finalize_kernel<<<1, 1>>>(out);
}

// round 6
// speedup vs baseline: 1.2894x; 1.2894x over previous
#include <cuda_runtime.h>
#include <cuda_bf16.h>
#include <math.h>
#include <stdint.h>

// Problem constants
constexpr int NN = 8192;
constexpr int DD = 1024;
constexpr float BD = 819.2f;   // 0.1 * n
constexpr float BU = 7372.8f;  // 0.9 * n

// ---------------- device scratch (static, allocation-free) ----------------
__device__ __nv_bfloat16 g_P0[(size_t)NN * NN];  // 128 MB, P0 = exp(L - 1)
__device__ __nv_bfloat16 g_Abf[(size_t)NN * DD]; // 16 MB
__device__ __nv_bfloat16 g_Bbf[(size_t)NN * DD]; // 16 MB
__device__ float g_c[NN], g_c2[NN];
__device__ float g_r[NN], g_r2[NN];
__device__ float g_u[NN], g_u2[NN];   // row sums; reused as CE S_img/S_txt accumulators
__device__ float g_s[NN], g_s2[NN];   // col sums
__device__ float g_diag[NN], g_diag2[NN];
__device__ float g_sums[1];

// ---------------- init ----------------
__global__ void init_kernel() {
    int i = blockIdx.x * blockDim.x + threadIdx.x;
    if (i < NN) {
        g_c[i] = 1.0f; g_c2[i] = 1.0f;
        g_u[i] = 0.0f; g_u2[i] = 0.0f;
        g_s[i] = 0.0f; g_s2[i] = 0.0f;
    }
    if (i == 0) g_sums[0] = 0.0f;
}

// ---------------- fp32 -> bf16 convert (vectorized) ----------------
__global__ __launch_bounds__(256) void convert_kernel(
    const float* __restrict__ A, const float* __restrict__ B) {
    int i = blockIdx.x * blockDim.x + threadIdx.x;  // float4 index
    const int n4 = NN * DD / 4;
    if (i < n4) {
        float4 va = reinterpret_cast<const float4*>(A)[i];
        __nv_bfloat162 a0 = __floats2bfloat162_rn(va.x, va.y);
        __nv_bfloat162 a1 = __floats2bfloat162_rn(va.z, va.w);
        reinterpret_cast<uint2*>(g_Abf)[i] =
            make_uint2(*reinterpret_cast<uint32_t*>(&a0),
                       *reinterpret_cast<uint32_t*>(&a1));
        float4 vb = reinterpret_cast<const float4*>(B)[i];
        __nv_bfloat162 b0 = __floats2bfloat162_rn(vb.x, vb.y);
        __nv_bfloat162 b1 = __floats2bfloat162_rn(vb.z, vb.w);
        reinterpret_cast<uint2*>(g_Bbf)[i] =
            make_uint2(*reinterpret_cast<uint32_t*>(&b0),
                       *reinterpret_cast<uint32_t*>(&b1));
    }
}

// ---------------- tensor-core GEMM (mma.sync): P0 = bf16(exp(A @ B^T - 1)) ----
// BM=BN=128, BK=64, 256 threads (8 warps: 2 m x 4 n), cp.async double buffer,
// SW128 swizzled smem, ldmatrix + mma.sync m16n8k16 bf16 -> fp32.
constexpr int BK = 64;
constexpr int KT = DD / BK;                // 16
constexpr int STAGE_BYTES = 2 * 128 * BK * 2;  // A tile + B tile = 32KB
constexpr int B_OFF = 128 * BK * 2;            // 16KB into stage

__device__ __forceinline__ void cp_async16(uint32_t s, const void* g) {
    asm volatile("cp.async.cg.shared.global [%0], [%1], 16;\n" :: "r"(s), "l"(g));
}
__device__ __forceinline__ void cp_commit() {
    asm volatile("cp.async.commit_group;\n");
}
template <int N>
__device__ __forceinline__ void cp_wait() {
    asm volatile("cp.async.wait_group %0;\n" :: "n"(N));
}
__device__ __forceinline__ void ldsm4(uint32_t& r0, uint32_t& r1, uint32_t& r2,
                                      uint32_t& r3, uint32_t addr) {
    asm volatile("ldmatrix.sync.aligned.m8n8.x4.shared.b16 {%0,%1,%2,%3}, [%4];\n"
                 : "=r"(r0), "=r"(r1), "=r"(r2), "=r"(r3) : "r"(addr));
}
__device__ __forceinline__ void mma16816(float* c, const uint32_t* a,
                                         const uint32_t* b) {
    asm volatile(
        "mma.sync.aligned.m16n8k16.row.col.f32.bf16.bf16.f32 "
        "{%0,%1,%2,%3}, {%4,%5,%6,%7}, {%8,%9}, {%0,%1,%2,%3};\n"
        : "+f"(c[0]), "+f"(c[1]), "+f"(c[2]), "+f"(c[3])
        : "r"(a[0]), "r"(a[1]), "r"(a[2]), "r"(a[3]), "r"(b[0]), "r"(b[1]));
}

__global__ __launch_bounds__(256) void gemm_bf16_exp_kernel() {
    extern __shared__ char smem[];
    const uint32_t sbase = (uint32_t)__cvta_generic_to_shared(smem);
    const int tid = threadIdx.x;
    const int wid = tid >> 5;
    const int lane = tid & 31;
    const int warp_m = wid & 1;   // 0..1, 64 rows each
    const int warp_n = wid >> 1;  // 0..3, 32 cols each
    const int bi = blockIdx.y * 128;
    const int bj = blockIdx.x * 128;

    float acc[4][4][4];
#pragma unroll
    for (int mt = 0; mt < 4; mt++)
#pragma unroll
        for (int nt = 0; nt < 4; nt++)
#pragma unroll
            for (int r = 0; r < 4; r++) acc[mt][nt][r] = 0.0f;

    auto load_stage = [&](int kt, int stage) {
        const int k0 = kt * BK;
        const uint32_t so = sbase + stage * STAGE_BYTES;
#pragma unroll
        for (int i = 0; i < 4; i++) {
            int u = tid + i * 256;
            int row = u >> 3;
            int chunk = u & 7;
            uint32_t d = so + row * 128 + ((chunk * 16) ^ ((row & 7) << 4));
            cp_async16(d, &g_Abf[(size_t)(bi + row) * DD + k0 + chunk * 8]);
            cp_async16(d + B_OFF, &g_Bbf[(size_t)(bj + row) * DD + k0 + chunk * 8]);
        }
        cp_commit();
    };

    load_stage(0, 0);

    for (int kt = 0; kt < KT; kt++) {
        const int stage = kt & 1;
        if (kt + 1 < KT) {
            load_stage(kt + 1, stage ^ 1);
            cp_wait<1>();
        } else {
            cp_wait<0>();
        }
        __syncthreads();

        const uint32_t sa = sbase + stage * STAGE_BYTES;
        const uint32_t sb = sa + B_OFF;
#pragma unroll
        for (int kk = 0; kk < BK / 16; kk++) {
            uint32_t a[4][4];
#pragma unroll
            for (int mt = 0; mt < 4; mt++) {
                int row = warp_m * 64 + mt * 16 + (lane & 15);
                int chunk = kk * 2 + (lane >> 4);
                uint32_t addr = sa + row * 128 + ((chunk * 16) ^ ((row & 7) << 4));
                ldsm4(a[mt][0], a[mt][1], a[mt][2], a[mt][3], addr);
            }
            uint32_t b[2][4];
#pragma unroll
            for (int pair = 0; pair < 2; pair++) {
                int rown = warp_n * 32 + pair * 16 + ((lane >> 4) << 3) + (lane & 7);
                int chunk = kk * 2 + ((lane >> 3) & 1);
                uint32_t addr = sb + rown * 128 + ((chunk * 16) ^ ((rown & 7) << 4));
                ldsm4(b[pair][0], b[pair][1], b[pair][2], b[pair][3], addr);
            }
#pragma unroll
            for (int mt = 0; mt < 4; mt++)
#pragma unroll
                for (int nt = 0; nt < 4; nt++)
                    mma16816(acc[mt][nt], a[mt], &b[nt >> 1][(nt & 1) * 2]);
        }
        __syncthreads();
    }

    // Epilogue: exp(x - 1) -> bf16, direct global stores (bf16x2 per reg pair)
    const int lrow = lane >> 2;
    const int lcol = (lane & 3) * 2;
#pragma unroll
    for (int mt = 0; mt < 4; mt++) {
#pragma unroll
        for (int nt = 0; nt < 4; nt++) {
            int gi0 = bi + warp_m * 64 + mt * 16 + lrow;
            int gj = bj + warp_n * 32 + nt * 8 + lcol;
            __nv_bfloat162 v0 = __floats2bfloat162_rn(
                __expf(acc[mt][nt][0] - 1.0f), __expf(acc[mt][nt][1] - 1.0f));
            __nv_bfloat162 v1 = __floats2bfloat162_rn(
                __expf(acc[mt][nt][2] - 1.0f), __expf(acc[mt][nt][3] - 1.0f));
            *reinterpret_cast<__nv_bfloat162*>(&g_P0[(size_t)gi0 * NN + gj]) = v0;
            *reinterpret_cast<__nv_bfloat162*>(&g_P0[(size_t)(gi0 + 8) * NN + gj]) = v1;
        }
    }
}

// ---------------- fused dual matvec (round-2 proven shape: uint2, ROWS=64) ----
// out_row[i] += sum_j P0[i][j] * f(a[j]);  out_col[j] += sum_i P0[i][j] * f(b[i])
// f(x) = 1/x when RECIP else x.  grid (8, 128) = 1024 blocks, regs=32, occ~80%.
template <bool RECIP>
__global__ __launch_bounds__(256) void dual_matvec_kernel(
    const float* __restrict__ a, const float* __restrict__ b,
    float* __restrict__ out_row, float* __restrict__ out_col) {
    const int ROWS = 64;
    const int tid = threadIdx.x;
    const int j = (blockIdx.x * 256 + tid) * 4;
    const int i0 = blockIdx.y * ROWS;
    __shared__ float bsh[ROWS];
    __shared__ float rowpart[ROWS][9];
    if (tid < ROWS) {
        float v = b[i0 + tid];
        bsh[tid] = RECIP ? 1.0f / v : v;
    }
    __syncthreads();

    float a0 = a[j], a1 = a[j + 1], a2 = a[j + 2], a3 = a[j + 3];
    if (RECIP) {
        a0 = 1.0f / a0; a1 = 1.0f / a1; a2 = 1.0f / a2; a3 = 1.0f / a3;
    }
    float c0 = 0.f, c1 = 0.f, c2 = 0.f, c3 = 0.f;
    const int warp = tid >> 5, lane = tid & 31;

    for (int ii = 0; ii < ROWS; ii++) {
        const __nv_bfloat16* p = g_P0 + (size_t)(i0 + ii) * NN + j;
        uint2 u = *reinterpret_cast<const uint2*>(p);
        __nv_bfloat162 x0 = *reinterpret_cast<__nv_bfloat162*>(&u.x);
        __nv_bfloat162 x1 = *reinterpret_cast<__nv_bfloat162*>(&u.y);
        float v0 = __bfloat162float(x0.x), v1 = __bfloat162float(x0.y);
        float v2 = __bfloat162float(x1.x), v3 = __bfloat162float(x1.y);
        float bi = bsh[ii];
        c0 = fmaf(v0, bi, c0); c1 = fmaf(v1, bi, c1);
        c2 = fmaf(v2, bi, c2); c3 = fmaf(v3, bi, c3);
        float rw = v0 * a0 + v1 * a1 + v2 * a2 + v3 * a3;
#pragma unroll
        for (int o = 16; o > 0; o >>= 1)
            rw += __shfl_down_sync(0xffffffffu, rw, o);
        if (lane == 0) rowpart[ii][warp] = rw;
    }
    __syncthreads();
    if (tid < ROWS) {
        float sacc = 0.f;
#pragma unroll
        for (int w = 0; w < 8; w++) sacc += rowpart[tid][w];
        atomicAdd(&out_row[i0 + tid], sacc);
    }
    atomicAdd(&out_col[j + 0], c0);
    atomicAdd(&out_col[j + 1], c1);
    atomicAdd(&out_col[j + 2], c2);
    atomicAdd(&out_col[j + 3], c3);
}

// colupd: r = 1/u (persists for CE), c/c2 two-step update from s/s2,
// then zero u,u2,s,s2 for the next iteration / CE accumulators.
__global__ void colupd_kernel() {
    int i = blockIdx.x * blockDim.x + threadIdx.x;
    if (i < NN) {
        g_r[i] = 1.0f / g_u[i];
        g_r2[i] = 1.0f / g_u2[i];
        float cv = g_c[i], sv = g_s[i];
        cv *= fmaxf(BD / (cv * sv), 1.0f);
        cv *= fminf(BU / (cv * sv), 1.0f);
        g_c[i] = cv;
        float cv2 = g_c2[i], sv2 = g_s2[i];
        cv2 *= fmaxf(BD / (cv2 * sv2), 1.0f);
        cv2 *= fminf(BU / (cv2 * sv2), 1.0f);
        g_c2[i] = cv2;
        g_u[i] = 0.0f; g_u2[i] = 0.0f;
        g_s[i] = 0.0f; g_s2[i] = 0.0f;
    }
}

// ---------------- fused CE: both directions in ONE read of P0 ----------------
// Image: S_img[i] = sum_j exp(r_i * P0_ij * c_j)      -> atomic into g_u
// Text:  S_txt[j] = sum_i exp(r2_j * P0_ij * c2_i)    -> atomic into g_u2
// diag:  g_diag[i] = r_i P0[i][lab_i] c[lab_i];  g_diag2[j] = r2_j P0[lab_j][j] c2[lab_j]
__global__ __launch_bounds__(256) void ce_fused_kernel(const int* __restrict__ labels) {
    const int ROWS = 64;
    const int tid = threadIdx.x;
    const int j = (blockIdx.x * 256 + tid) * 8;
    const int i0 = blockIdx.y * ROWS;
    __shared__ float rsh[ROWS], c2sh[ROWS];
    __shared__ int labsh[ROWS];
    __shared__ float rowpart[ROWS][9];
    if (tid < ROWS) {
        rsh[tid] = g_r[i0 + tid];
        c2sh[tid] = g_c2[i0 + tid];
        labsh[tid] = labels[i0 + tid];
    }
    __syncthreads();

    float cj[8], r2j[8];
    int labc[8];
    {
        float4 t0 = *reinterpret_cast<const float4*>(&g_c[j]);
        float4 t1 = *reinterpret_cast<const float4*>(&g_c[j + 4]);
        cj[0] = t0.x; cj[1] = t0.y; cj[2] = t0.z; cj[3] = t0.w;
        cj[4] = t1.x; cj[5] = t1.y; cj[6] = t1.z; cj[7] = t1.w;
        t0 = *reinterpret_cast<const float4*>(&g_r2[j]);
        t1 = *reinterpret_cast<const float4*>(&g_r2[j + 4]);
        r2j[0] = t0.x; r2j[1] = t0.y; r2j[2] = t0.z; r2j[3] = t0.w;
        r2j[4] = t1.x; r2j[5] = t1.y; r2j[6] = t1.z; r2j[7] = t1.w;
        int4 l0 = *reinterpret_cast<const int4*>(&labels[j]);
        int4 l1 = *reinterpret_cast<const int4*>(&labels[j + 4]);
        labc[0] = l0.x; labc[1] = l0.y; labc[2] = l0.z; labc[3] = l0.w;
        labc[4] = l1.x; labc[5] = l1.y; labc[6] = l1.z; labc[7] = l1.w;
    }
    float colacc[8];
#pragma unroll
    for (int k = 0; k < 8; k++) colacc[k] = 0.0f;
    const int warp = tid >> 5, lane = tid & 31;
    const __nv_bfloat16* base = g_P0 + (size_t)i0 * NN + j;

    for (int ii = 0; ii < ROWS; ii++) {
        uint4 u = *reinterpret_cast<const uint4*>(base + (size_t)ii * NN);
        float v[8];
        {
            float2 f;
            f = __bfloat1622float2(*reinterpret_cast<__nv_bfloat162*>(&u.x));
            v[0] = f.x; v[1] = f.y;
            f = __bfloat1622float2(*reinterpret_cast<__nv_bfloat162*>(&u.y));
            v[2] = f.x; v[3] = f.y;
            f = __bfloat1622float2(*reinterpret_cast<__nv_bfloat162*>(&u.z));
            v[4] = f.x; v[5] = f.y;
            f = __bfloat1622float2(*reinterpret_cast<__nv_bfloat162*>(&u.w));
            v[6] = f.x; v[7] = f.y;
        }
        const int irow = i0 + ii;
        const float ri = rsh[ii], c2i = c2sh[ii];
        const int labr = labsh[ii];
        float rdot = 0.0f;
#pragma unroll
        for (int k = 0; k < 8; k++) {
            float e1 = ri * v[k] * cj[k];
            float e2 = r2j[k] * v[k] * c2i;
            rdot += __expf(e1);
            colacc[k] += __expf(e2);
            if (j + k == labr) g_diag[irow] = e1;
            if (irow == labc[k]) g_diag2[j + k] = e2;
        }
#pragma unroll
        for (int o = 16; o > 0; o >>= 1)
            rdot += __shfl_down_sync(0xffffffffu, rdot, o);
        if (lane == 0) rowpart[ii][warp] = rdot;
    }
    __syncthreads();
    if (tid < ROWS) {
        float sacc = 0.f;
#pragma unroll
        for (int w = 0; w < 8; w++) sacc += rowpart[tid][w];
        atomicAdd(&g_u[i0 + tid], sacc);
    }
#pragma unroll
    for (int k = 0; k < 8; k++) atomicAdd(&g_u2[j + k], colacc[k]);
}

__global__ __launch_bounds__(256) void ce_reduce_kernel() {
    int t = blockIdx.x * 256 + threadIdx.x;
    float v = (logf(g_u[t]) - g_diag[t]) + (logf(g_u2[t]) - g_diag2[t]);
    __shared__ float wsum[8];
#pragma unroll
    for (int o = 16; o > 0; o >>= 1)
        v += __shfl_down_sync(0xffffffffu, v, o);
    int warp = threadIdx.x >> 5, lane = threadIdx.x & 31;
    if (lane == 0) wsum[warp] = v;
    __syncthreads();
    if (threadIdx.x == 0) {
        float tt = 0.f;
#pragma unroll
        for (int w = 0; w < 8; w++) tt += wsum[w];
        atomicAdd(&g_sums[0], tt);
    }
}

__global__ void finalize_kernel(float* __restrict__ out) {
    out[0] = g_sums[0] / (2.0f * (float)NN);
}

// ---------------- launch ----------------
extern "C" void kernel_launch(void* const* d_in, const int* in_sizes, int n_in,
                              void* d_out, int out_size) {
    const float* A = (const float*)d_in[0];   // all_image_features [N, D]
    const float* B = (const float*)d_in[1];   // all_text_features  [N, D]
    const int* labels = (const int*)d_in[3];
    float* out = (float*)d_out;

    float *c, *c2, *u, *u2, *s, *s2;
    cudaGetSymbolAddress((void**)&c, g_c);
    cudaGetSymbolAddress((void**)&c2, g_c2);
    cudaGetSymbolAddress((void**)&u, g_u);
    cudaGetSymbolAddress((void**)&u2, g_u2);
    cudaGetSymbolAddress((void**)&s, g_s);
    cudaGetSymbolAddress((void**)&s2, g_s2);

    cudaFuncSetAttribute(gemm_bf16_exp_kernel,
                         cudaFuncAttributeMaxDynamicSharedMemorySize,
                         2 * STAGE_BYTES);

    init_kernel<<<NN / 256, 256>>>();
    convert_kernel<<<NN * DD / 4 / 256, 256>>>(A, B);
    gemm_bf16_exp_kernel<<<dim3(64, 64), 256, 2 * STAGE_BYTES>>>();

    for (int it = 0; it < 5; it++) {
        // pass1: u_i += sum_j P0_ij c_j ; u2_j += sum_i P0_ij c2_i
        dual_matvec_kernel<false><<<dim3(8, 128), 256>>>(c, c2, u, u2);
        // pass2: s2_i += sum_j P0_ij (1/u2_j) ; s_j += sum_i P0_ij (1/u_i)
        dual_matvec_kernel<true><<<dim3(8, 128), 256>>>(u2, u, s2, s);
        colupd_kernel<<<NN / 256, 256>>>();
    }

    ce_fused_kernel<<<dim3(4, 128), 256>>>(labels);
    ce_reduce_kernel<<<NN / 256, 256>>>();
    finalize_kernel<<<1, 1>>>(out);
}

// round 7
// speedup vs baseline: 1.3151x; 1.0200x over previous
#include <cuda_runtime.h>
#include <cuda_bf16.h>
#include <cuda_fp16.h>
#include <math.h>
#include <stdint.h>

// Problem constants
constexpr int NN = 8192;
constexpr int DD = 1024;
constexpr float BD = 819.2f;   // 0.1 * n
constexpr float BU = 7372.8f;  // 0.9 * n
constexpr float INSCALE = 16.0f;        // input quantization scale
constexpr float ACCSCALE = 1.0f / 256.0f;  // 1/(16*16)

// ---------------- device scratch (static, allocation-free) ----------------
__device__ uint8_t g_P0[(size_t)NN * NN];   // 64 MB, e4m3 of exp(L - 1)
__device__ uint8_t g_A8[(size_t)NN * DD];   // 8 MB, e4m3 of 16*A
__device__ uint8_t g_B8[(size_t)NN * DD];   // 8 MB, e4m3 of 16*B
__device__ float g_c[NN], g_c2[NN];
__device__ float g_r[NN], g_r2[NN];
__device__ float g_u[NN], g_u2[NN];   // row sums; reused as CE S accumulators
__device__ float g_s[NN], g_s2[NN];   // col sums
__device__ float g_diag[NN], g_diag2[NN];
__device__ float g_sums[1];

// ---------------- fp8 helpers (sm_89+ instructions, safe on sm_100 base) ----
__device__ __forceinline__ unsigned short f32x2_to_e4m3x2(float lo, float hi) {
    unsigned short r;
    asm("cvt.rn.satfinite.e4m3x2.f32 %0, %1, %2;" : "=h"(r) : "f"(hi), "f"(lo));
    return r;
}
// decode 4 packed e4m3 (one u32) -> 4 floats, v[0] = byte0
__device__ __forceinline__ void e4m3x4_to_f32(uint32_t u, float* v) {
    uint32_t h0, h1;
    asm("cvt.rn.f16x2.e4m3x2 %0, %1;" : "=r"(h0)
        : "h"((unsigned short)(u & 0xffffu)));
    asm("cvt.rn.f16x2.e4m3x2 %0, %1;" : "=r"(h1)
        : "h"((unsigned short)(u >> 16)));
    float2 f0 = __half22float2(*reinterpret_cast<__half2*>(&h0));
    float2 f1 = __half22float2(*reinterpret_cast<__half2*>(&h1));
    v[0] = f0.x; v[1] = f0.y; v[2] = f1.x; v[3] = f1.y;
}

// ---------------- init ----------------
__global__ void init_kernel() {
    int i = blockIdx.x * blockDim.x + threadIdx.x;
    if (i < NN) {
        g_c[i] = 1.0f; g_c2[i] = 1.0f;
        g_u[i] = 0.0f; g_u2[i] = 0.0f;
        g_s[i] = 0.0f; g_s2[i] = 0.0f;
    }
    if (i == 0) g_sums[0] = 0.0f;
}

// ---------------- fp32 -> e4m3 convert (scale 16) ----------------
__global__ __launch_bounds__(256) void convert_kernel(
    const float* __restrict__ A, const float* __restrict__ B) {
    int i = blockIdx.x * blockDim.x + threadIdx.x;  // float4 index
    const int n4 = NN * DD / 4;
    if (i < n4) {
        float4 va = reinterpret_cast<const float4*>(A)[i];
        uint32_t pa = (uint32_t)f32x2_to_e4m3x2(va.x * INSCALE, va.y * INSCALE) |
                      ((uint32_t)f32x2_to_e4m3x2(va.z * INSCALE, va.w * INSCALE) << 16);
        reinterpret_cast<uint32_t*>(g_A8)[i] = pa;
        float4 vb = reinterpret_cast<const float4*>(B)[i];
        uint32_t pb = (uint32_t)f32x2_to_e4m3x2(vb.x * INSCALE, vb.y * INSCALE) |
                      ((uint32_t)f32x2_to_e4m3x2(vb.z * INSCALE, vb.w * INSCALE) << 16);
        reinterpret_cast<uint32_t*>(g_B8)[i] = pb;
    }
}

// ---------------- fp8 tensor-core GEMM: P0 = e4m3(exp(acc/256 - 1)) ----------
// BM=BN=128, K-stage = 128 fp8 (128-byte rows, SW128), double buffer,
// ldmatrix.b16 on pair-packed fp8 + mma.sync m16n8k32 e4m3 -> fp32.
constexpr int KSTG = 128;                 // K elements (bytes) per stage
constexpr int KT = DD / KSTG;             // 8
constexpr int STAGE_BYTES = 2 * 128 * 128;  // A tile + B tile = 32KB
constexpr int B_OFF = 128 * 128;            // 16KB

__device__ __forceinline__ void cp_async16(uint32_t s, const void* g) {
    asm volatile("cp.async.cg.shared.global [%0], [%1], 16;\n" :: "r"(s), "l"(g));
}
__device__ __forceinline__ void cp_commit() {
    asm volatile("cp.async.commit_group;\n");
}
template <int N>
__device__ __forceinline__ void cp_wait() {
    asm volatile("cp.async.wait_group %0;\n" :: "n"(N));
}
__device__ __forceinline__ void ldsm4(uint32_t& r0, uint32_t& r1, uint32_t& r2,
                                      uint32_t& r3, uint32_t addr) {
    asm volatile("ldmatrix.sync.aligned.m8n8.x4.shared.b16 {%0,%1,%2,%3}, [%4];\n"
                 : "=r"(r0), "=r"(r1), "=r"(r2), "=r"(r3) : "r"(addr));
}
__device__ __forceinline__ void mma16832_e4m3(float* c, const uint32_t* a,
                                              const uint32_t* b) {
    asm volatile(
        "mma.sync.aligned.m16n8k32.row.col.f32.e4m3.e4m3.f32 "
        "{%0,%1,%2,%3}, {%4,%5,%6,%7}, {%8,%9}, {%0,%1,%2,%3};\n"
        : "+f"(c[0]), "+f"(c[1]), "+f"(c[2]), "+f"(c[3])
        : "r"(a[0]), "r"(a[1]), "r"(a[2]), "r"(a[3]), "r"(b[0]), "r"(b[1]));
}

__global__ __launch_bounds__(256) void gemm_fp8_exp_kernel() {
    extern __shared__ char smem[];
    const uint32_t sbase = (uint32_t)__cvta_generic_to_shared(smem);
    const int tid = threadIdx.x;
    const int wid = tid >> 5;
    const int lane = tid & 31;
    const int warp_m = wid & 1;   // 0..1, 64 rows each
    const int warp_n = wid >> 1;  // 0..3, 32 cols each
    const int bi = blockIdx.y * 128;
    const int bj = blockIdx.x * 128;

    float acc[4][4][4];
#pragma unroll
    for (int mt = 0; mt < 4; mt++)
#pragma unroll
        for (int nt = 0; nt < 4; nt++)
#pragma unroll
            for (int r = 0; r < 4; r++) acc[mt][nt][r] = 0.0f;

    auto load_stage = [&](int kt, int stage) {
        const int k0 = kt * KSTG;
        const uint32_t so = sbase + stage * STAGE_BYTES;
#pragma unroll
        for (int i = 0; i < 4; i++) {
            int u = tid + i * 256;   // 1024 16B units per tile
            int row = u >> 3;
            int chunk = u & 7;
            uint32_t d = so + row * 128 + ((chunk * 16) ^ ((row & 7) << 4));
            cp_async16(d, &g_A8[(size_t)(bi + row) * DD + k0 + chunk * 16]);
            cp_async16(d + B_OFF, &g_B8[(size_t)(bj + row) * DD + k0 + chunk * 16]);
        }
        cp_commit();
    };

    load_stage(0, 0);

    for (int kt = 0; kt < KT; kt++) {
        const int stage = kt & 1;
        if (kt + 1 < KT) {
            load_stage(kt + 1, stage ^ 1);
            cp_wait<1>();
        } else {
            cp_wait<0>();
        }
        __syncthreads();

        const uint32_t sa = sbase + stage * STAGE_BYTES;
        const uint32_t sb = sa + B_OFF;
#pragma unroll
        for (int kk = 0; kk < 4; kk++) {   // each kk: K=32 fp8 = 2 chunks
            uint32_t a[4][4];
#pragma unroll
            for (int mt = 0; mt < 4; mt++) {
                int row = warp_m * 64 + mt * 16 + (lane & 15);
                int chunk = kk * 2 + (lane >> 4);
                uint32_t addr = sa + row * 128 + ((chunk * 16) ^ ((row & 7) << 4));
                ldsm4(a[mt][0], a[mt][1], a[mt][2], a[mt][3], addr);
            }
            uint32_t b[2][4];
#pragma unroll
            for (int pair = 0; pair < 2; pair++) {
                int rown = warp_n * 32 + pair * 16 + ((lane >> 4) << 3) + (lane & 7);
                int chunk = kk * 2 + ((lane >> 3) & 1);
                uint32_t addr = sb + rown * 128 + ((chunk * 16) ^ ((rown & 7) << 4));
                ldsm4(b[pair][0], b[pair][1], b[pair][2], b[pair][3], addr);
            }
#pragma unroll
            for (int mt = 0; mt < 4; mt++)
#pragma unroll
                for (int nt = 0; nt < 4; nt++)
                    mma16832_e4m3(acc[mt][nt], a[mt], &b[nt >> 1][(nt & 1) * 2]);
        }
        __syncthreads();
    }

    // Epilogue: exp(acc/256 - 1) -> e4m3, 16-bit stores (2 cols per pair)
    const int lrow = lane >> 2;
    const int lcol = (lane & 3) * 2;
#pragma unroll
    for (int mt = 0; mt < 4; mt++) {
#pragma unroll
        for (int nt = 0; nt < 4; nt++) {
            int gi0 = bi + warp_m * 64 + mt * 16 + lrow;
            int gj = bj + warp_n * 32 + nt * 8 + lcol;
            unsigned short p0 = f32x2_to_e4m3x2(
                __expf(acc[mt][nt][0] * ACCSCALE - 1.0f),
                __expf(acc[mt][nt][1] * ACCSCALE - 1.0f));
            unsigned short p1 = f32x2_to_e4m3x2(
                __expf(acc[mt][nt][2] * ACCSCALE - 1.0f),
                __expf(acc[mt][nt][3] * ACCSCALE - 1.0f));
            *reinterpret_cast<unsigned short*>(&g_P0[(size_t)gi0 * NN + gj]) = p0;
            *reinterpret_cast<unsigned short*>(&g_P0[(size_t)(gi0 + 8) * NN + gj]) = p1;
        }
    }
}

// ---------------- fused dual matvec on fp8 P0 ----------------
// out_row[i] += sum_j P0[i][j] * f(a[j]);  out_col[j] += sum_i P0[i][j] * f(b[i])
// f(x) = 1/x when RECIP else x. 4 cols/thread (u32 load), 2-row interleave.
template <bool RECIP>
__global__ __launch_bounds__(256) void dual_matvec_kernel(
    const float* __restrict__ a, const float* __restrict__ b,
    float* __restrict__ out_row, float* __restrict__ out_col) {
    const int ROWS = 64;
    const int tid = threadIdx.x;
    const int j = (blockIdx.x * 256 + tid) * 4;
    const int i0 = blockIdx.y * ROWS;
    __shared__ float bsh[ROWS];
    __shared__ float rowpart[ROWS][9];
    if (tid < ROWS) {
        float v = b[i0 + tid];
        bsh[tid] = RECIP ? 1.0f / v : v;
    }
    __syncthreads();

    float a0 = a[j], a1 = a[j + 1], a2 = a[j + 2], a3 = a[j + 3];
    if (RECIP) {
        a0 = 1.0f / a0; a1 = 1.0f / a1; a2 = 1.0f / a2; a3 = 1.0f / a3;
    }
    float c0 = 0.f, c1 = 0.f, c2 = 0.f, c3 = 0.f;
    const int warp = tid >> 5, lane = tid & 31;
    const uint8_t* base = g_P0 + (size_t)i0 * NN + j;

    for (int ii = 0; ii < ROWS; ii += 2) {
        uint32_t u0 = *reinterpret_cast<const uint32_t*>(base + (size_t)ii * NN);
        uint32_t u1 = *reinterpret_cast<const uint32_t*>(base + (size_t)(ii + 1) * NN);
        float v0[4], v1[4];
        e4m3x4_to_f32(u0, v0);
        e4m3x4_to_f32(u1, v1);
        float b0 = bsh[ii], b1 = bsh[ii + 1];
        c0 = fmaf(v0[0], b0, c0); c1 = fmaf(v0[1], b0, c1);
        c2 = fmaf(v0[2], b0, c2); c3 = fmaf(v0[3], b0, c3);
        c0 = fmaf(v1[0], b1, c0); c1 = fmaf(v1[1], b1, c1);
        c2 = fmaf(v1[2], b1, c2); c3 = fmaf(v1[3], b1, c3);
        float d0 = v0[0] * a0 + v0[1] * a1 + v0[2] * a2 + v0[3] * a3;
        float d1 = v1[0] * a0 + v1[1] * a1 + v1[2] * a2 + v1[3] * a3;
#pragma unroll
        for (int o = 16; o > 0; o >>= 1) {
            d0 += __shfl_down_sync(0xffffffffu, d0, o);
            d1 += __shfl_down_sync(0xffffffffu, d1, o);
        }
        if (lane == 0) {
            rowpart[ii][warp] = d0;
            rowpart[ii + 1][warp] = d1;
        }
    }
    __syncthreads();
    if (tid < ROWS) {
        float sacc = 0.f;
#pragma unroll
        for (int w = 0; w < 8; w++) sacc += rowpart[tid][w];
        atomicAdd(&out_row[i0 + tid], sacc);
    }
    atomicAdd(&out_col[j + 0], c0);
    atomicAdd(&out_col[j + 1], c1);
    atomicAdd(&out_col[j + 2], c2);
    atomicAdd(&out_col[j + 3], c3);
}

// colupd: r = 1/u (persists for CE), c/c2 two-step update from s/s2,
// then zero u,u2,s,s2 for next iteration / CE accumulators.
__global__ void colupd_kernel() {
    int i = blockIdx.x * blockDim.x + threadIdx.x;
    if (i < NN) {
        g_r[i] = 1.0f / g_u[i];
        g_r2[i] = 1.0f / g_u2[i];
        float cv = g_c[i], sv = g_s[i];
        cv *= fmaxf(BD / (cv * sv), 1.0f);
        cv *= fminf(BU / (cv * sv), 1.0f);
        g_c[i] = cv;
        float cv2 = g_c2[i], sv2 = g_s2[i];
        cv2 *= fmaxf(BD / (cv2 * sv2), 1.0f);
        cv2 *= fminf(BU / (cv2 * sv2), 1.0f);
        g_c2[i] = cv2;
        g_u[i] = 0.0f; g_u2[i] = 0.0f;
        g_s[i] = 0.0f; g_s2[i] = 0.0f;
    }
}

// ---------------- fused CE: both directions in ONE read of fp8 P0 ----------
__global__ __launch_bounds__(256) void ce_fused_kernel(const int* __restrict__ labels) {
    const int ROWS = 64;
    const int tid = threadIdx.x;
    const int j = (blockIdx.x * 256 + tid) * 8;
    const int i0 = blockIdx.y * ROWS;
    __shared__ float rsh[ROWS], c2sh[ROWS];
    __shared__ int labsh[ROWS];
    __shared__ float rowpart[ROWS][9];
    if (tid < ROWS) {
        rsh[tid] = g_r[i0 + tid];
        c2sh[tid] = g_c2[i0 + tid];
        labsh[tid] = labels[i0 + tid];
    }
    __syncthreads();

    float cj[8], r2j[8];
    int labc[8];
    {
        float4 t0 = *reinterpret_cast<const float4*>(&g_c[j]);
        float4 t1 = *reinterpret_cast<const float4*>(&g_c[j + 4]);
        cj[0] = t0.x; cj[1] = t0.y; cj[2] = t0.z; cj[3] = t0.w;
        cj[4] = t1.x; cj[5] = t1.y; cj[6] = t1.z; cj[7] = t1.w;
        t0 = *reinterpret_cast<const float4*>(&g_r2[j]);
        t1 = *reinterpret_cast<const float4*>(&g_r2[j + 4]);
        r2j[0] = t0.x; r2j[1] = t0.y; r2j[2] = t0.z; r2j[3] = t0.w;
        r2j[4] = t1.x; r2j[5] = t1.y; r2j[6] = t1.z; r2j[7] = t1.w;
        int4 l0 = *reinterpret_cast<const int4*>(&labels[j]);
        int4 l1 = *reinterpret_cast<const int4*>(&labels[j + 4]);
        labc[0] = l0.x; labc[1] = l0.y; labc[2] = l0.z; labc[3] = l0.w;
        labc[4] = l1.x; labc[5] = l1.y; labc[6] = l1.z; labc[7] = l1.w;
    }
    float colacc[8];
#pragma unroll
    for (int k = 0; k < 8; k++) colacc[k] = 0.0f;
    const int warp = tid >> 5, lane = tid & 31;
    const uint8_t* base = g_P0 + (size_t)i0 * NN + j;

    for (int ii = 0; ii < ROWS; ii++) {
        uint2 u = *reinterpret_cast<const uint2*>(base + (size_t)ii * NN);
        float v[8];
        e4m3x4_to_f32(u.x, v);
        e4m3x4_to_f32(u.y, v + 4);
        const int irow = i0 + ii;
        const float ri = rsh[ii], c2i = c2sh[ii];
        const int labr = labsh[ii];
        float rdot = 0.0f;
#pragma unroll
        for (int k = 0; k < 8; k++) {
            float e1 = ri * v[k] * cj[k];
            float e2 = r2j[k] * v[k] * c2i;
            rdot += __expf(e1);
            colacc[k] += __expf(e2);
            if (j + k == labr) g_diag[irow] = e1;
            if (irow == labc[k]) g_diag2[j + k] = e2;
        }
#pragma unroll
        for (int o = 16; o > 0; o >>= 1)
            rdot += __shfl_down_sync(0xffffffffu, rdot, o);
        if (lane == 0) rowpart[ii][warp] = rdot;
    }
    __syncthreads();
    if (tid < ROWS) {
        float sacc = 0.f;
#pragma unroll
        for (int w = 0; w < 8; w++) sacc += rowpart[tid][w];
        atomicAdd(&g_u[i0 + tid], sacc);
    }
#pragma unroll
    for (int k = 0; k < 8; k++) atomicAdd(&g_u2[j + k], colacc[k]);
}

__global__ __launch_bounds__(256) void ce_reduce_kernel() {
    int t = blockIdx.x * 256 + threadIdx.x;
    float v = (logf(g_u[t]) - g_diag[t]) + (logf(g_u2[t]) - g_diag2[t]);
    __shared__ float wsum[8];
#pragma unroll
    for (int o = 16; o > 0; o >>= 1)
        v += __shfl_down_sync(0xffffffffu, v, o);
    int warp = threadIdx.x >> 5, lane = threadIdx.x & 31;
    if (lane == 0) wsum[warp] = v;
    __syncthreads();
    if (threadIdx.x == 0) {
        float tt = 0.f;
#pragma unroll
        for (int w = 0; w < 8; w++) tt += wsum[w];
        atomicAdd(&g_sums[0], tt);
    }
}

__global__ void finalize_kernel(float* __restrict__ out) {
    out[0] = g_sums[0] / (2.0f * (float)NN);
}

// ---------------- launch ----------------
extern "C" void kernel_launch(void* const* d_in, const int* in_sizes, int n_in,
                              void* d_out, int out_size) {
    const float* A = (const float*)d_in[0];   // all_image_features [N, D]
    const float* B = (const float*)d_in[1];   // all_text_features  [N, D]
    const int* labels = (const int*)d_in[3];
    float* out = (float*)d_out;

    float *c, *c2, *u, *u2, *s, *s2;
    cudaGetSymbolAddress((void**)&c, g_c);
    cudaGetSymbolAddress((void**)&c2, g_c2);
    cudaGetSymbolAddress((void**)&u, g_u);
    cudaGetSymbolAddress((void**)&u2, g_u2);
    cudaGetSymbolAddress((void**)&s, g_s);
    cudaGetSymbolAddress((void**)&s2, g_s2);

    cudaFuncSetAttribute(gemm_fp8_exp_kernel,
                         cudaFuncAttributeMaxDynamicSharedMemorySize,
                         2 * STAGE_BYTES);

    init_kernel<<<NN / 256, 256>>>();
    convert_kernel<<<NN * DD / 4 / 256, 256>>>(A, B);
    gemm_fp8_exp_kernel<<<dim3(64, 64), 256, 2 * STAGE_BYTES>>>();

    for (int it = 0; it < 5; it++) {
        // pass1: u_i += sum_j P0_ij c_j ; u2_j += sum_i P0_ij c2_i
        dual_matvec_kernel<false><<<dim3(8, 128), 256>>>(c, c2, u, u2);
        // pass2: s2_i += sum_j P0_ij (1/u2_j) ; s_j += sum_i P0_ij (1/u_i)
        dual_matvec_kernel<true><<<dim3(8, 128), 256>>>(u2, u, s2, s);
        colupd_kernel<<<NN / 256, 256>>>();
    }

    ce_fused_kernel<<<dim3(4, 128), 256>>>(labels);
    ce_reduce_kernel<<<NN / 256, 256>>>();
    finalize_kernel<<<1, 1>>>(out);
}

// round 8
// speedup vs baseline: 1.8876x; 1.4353x over previous
#include <cuda_runtime.h>
#include <cuda_bf16.h>
#include <cuda_fp16.h>
#include <math.h>
#include <stdint.h>

// Problem constants
constexpr int NN = 8192;
constexpr int DD = 1024;
constexpr float BD = 819.2f;   // 0.1 * n
constexpr float BU = 7372.8f;  // 0.9 * n
constexpr float INSCALE = 256.0f;            // int8 quantization scale
constexpr float ACCSCALE = 1.0f / 65536.0f;  // 1/(256*256)

// ---------------- device scratch (static, allocation-free) ----------------
__device__ uint8_t g_P0[(size_t)NN * NN];   // 64 MB, e4m3 of exp(L - 1)
__device__ int8_t g_A8[(size_t)NN * DD];    // 8 MB, int8 of 256*A
__device__ int8_t g_B8[(size_t)NN * DD];    // 8 MB, int8 of 256*B
__device__ float g_c[NN], g_c2[NN];
__device__ float g_r[NN], g_r2[NN];
__device__ float g_u[NN], g_u2[NN];   // row sums; reused as CE S accumulators
__device__ float g_s[NN], g_s2[NN];   // col sums
__device__ float g_diag[NN], g_diag2[NN];
__device__ float g_sums[1];

// ---------------- fp8 helpers (sm_89+ instructions) ----------------
__device__ __forceinline__ unsigned short f32x2_to_e4m3x2(float lo, float hi) {
    unsigned short r;
    asm("cvt.rn.satfinite.e4m3x2.f32 %0, %1, %2;" : "=h"(r) : "f"(hi), "f"(lo));
    return r;
}
// decode 4 packed e4m3 (one u32) -> 4 floats, v[0] = byte0
__device__ __forceinline__ void e4m3x4_to_f32(uint32_t u, float* v) {
    uint32_t h0, h1;
    asm("cvt.rn.f16x2.e4m3x2 %0, %1;" : "=r"(h0)
        : "h"((unsigned short)(u & 0xffffu)));
    asm("cvt.rn.f16x2.e4m3x2 %0, %1;" : "=r"(h1)
        : "h"((unsigned short)(u >> 16)));
    float2 f0 = __half22float2(*reinterpret_cast<__half2*>(&h0));
    float2 f1 = __half22float2(*reinterpret_cast<__half2*>(&h1));
    v[0] = f0.x; v[1] = f0.y; v[2] = f1.x; v[3] = f1.y;
}

// ---------------- init ----------------
__global__ void init_kernel() {
    int i = blockIdx.x * blockDim.x + threadIdx.x;
    if (i < NN) {
        g_c[i] = 1.0f; g_c2[i] = 1.0f;
        g_u[i] = 0.0f; g_u2[i] = 0.0f;
        g_s[i] = 0.0f; g_s2[i] = 0.0f;
    }
    if (i == 0) g_sums[0] = 0.0f;
}

// ---------------- fp32 -> int8 convert (scale 256) ----------------
__device__ __forceinline__ uint32_t quant4(float4 v) {
    int i0 = __float2int_rn(fminf(fmaxf(v.x * INSCALE, -127.f), 127.f));
    int i1 = __float2int_rn(fminf(fmaxf(v.y * INSCALE, -127.f), 127.f));
    int i2 = __float2int_rn(fminf(fmaxf(v.z * INSCALE, -127.f), 127.f));
    int i3 = __float2int_rn(fminf(fmaxf(v.w * INSCALE, -127.f), 127.f));
    return (uint32_t)(i0 & 255) | ((uint32_t)(i1 & 255) << 8) |
           ((uint32_t)(i2 & 255) << 16) | ((uint32_t)(i3 & 255) << 24);
}
__global__ __launch_bounds__(256) void convert_kernel(
    const float* __restrict__ A, const float* __restrict__ B) {
    int i = blockIdx.x * blockDim.x + threadIdx.x;  // float4 index
    const int n4 = NN * DD / 4;
    if (i < n4) {
        reinterpret_cast<uint32_t*>(g_A8)[i] =
            quant4(reinterpret_cast<const float4*>(A)[i]);
        reinterpret_cast<uint32_t*>(g_B8)[i] =
            quant4(reinterpret_cast<const float4*>(B)[i]);
    }
}

// ---------------- int8 tensor-core GEMM: P0 = e4m3(exp(acc/65536 - 1)) ------
// BM=BN=128, K-stage = 128 int8 (128-byte rows, SW128), double buffer,
// ldmatrix.b16 on pair-packed int8 + mma.sync m16n8k32 s8 -> s32 (exact).
constexpr int KSTG = 128;                 // K elements (bytes) per stage
constexpr int KT = DD / KSTG;             // 8
constexpr int STAGE_BYTES = 2 * 128 * 128;  // A tile + B tile = 32KB
constexpr int B_OFF = 128 * 128;            // 16KB

__device__ __forceinline__ void cp_async16(uint32_t s, const void* g) {
    asm volatile("cp.async.cg.shared.global [%0], [%1], 16;\n" :: "r"(s), "l"(g));
}
__device__ __forceinline__ void cp_commit() {
    asm volatile("cp.async.commit_group;\n");
}
template <int N>
__device__ __forceinline__ void cp_wait() {
    asm volatile("cp.async.wait_group %0;\n" :: "n"(N));
}
__device__ __forceinline__ void ldsm4(uint32_t& r0, uint32_t& r1, uint32_t& r2,
                                      uint32_t& r3, uint32_t addr) {
    asm volatile("ldmatrix.sync.aligned.m8n8.x4.shared.b16 {%0,%1,%2,%3}, [%4];\n"
                 : "=r"(r0), "=r"(r1), "=r"(r2), "=r"(r3) : "r"(addr));
}
__device__ __forceinline__ void mma16832_s8(int* c, const uint32_t* a,
                                            const uint32_t* b) {
    asm volatile(
        "mma.sync.aligned.m16n8k32.row.col.s32.s8.s8.s32 "
        "{%0,%1,%2,%3}, {%4,%5,%6,%7}, {%8,%9}, {%0,%1,%2,%3};\n"
        : "+r"(c[0]), "+r"(c[1]), "+r"(c[2]), "+r"(c[3])
        : "r"(a[0]), "r"(a[1]), "r"(a[2]), "r"(a[3]), "r"(b[0]), "r"(b[1]));
}

__global__ __launch_bounds__(256) void gemm_i8_exp_kernel() {
    extern __shared__ char smem[];
    const uint32_t sbase = (uint32_t)__cvta_generic_to_shared(smem);
    const int tid = threadIdx.x;
    const int wid = tid >> 5;
    const int lane = tid & 31;
    const int warp_m = wid & 1;   // 0..1, 64 rows each
    const int warp_n = wid >> 1;  // 0..3, 32 cols each
    const int bi = blockIdx.y * 128;
    const int bj = blockIdx.x * 128;

    int acc[4][4][4];
#pragma unroll
    for (int mt = 0; mt < 4; mt++)
#pragma unroll
        for (int nt = 0; nt < 4; nt++)
#pragma unroll
            for (int r = 0; r < 4; r++) acc[mt][nt][r] = 0;

    auto load_stage = [&](int kt, int stage) {
        const int k0 = kt * KSTG;
        const uint32_t so = sbase + stage * STAGE_BYTES;
#pragma unroll
        for (int i = 0; i < 4; i++) {
            int u = tid + i * 256;   // 1024 16B units per tile
            int row = u >> 3;
            int chunk = u & 7;
            uint32_t d = so + row * 128 + ((chunk * 16) ^ ((row & 7) << 4));
            cp_async16(d, &g_A8[(size_t)(bi + row) * DD + k0 + chunk * 16]);
            cp_async16(d + B_OFF, &g_B8[(size_t)(bj + row) * DD + k0 + chunk * 16]);
        }
        cp_commit();
    };

    load_stage(0, 0);

    for (int kt = 0; kt < KT; kt++) {
        const int stage = kt & 1;
        if (kt + 1 < KT) {
            load_stage(kt + 1, stage ^ 1);
            cp_wait<1>();
        } else {
            cp_wait<0>();
        }
        __syncthreads();

        const uint32_t sa = sbase + stage * STAGE_BYTES;
        const uint32_t sb = sa + B_OFF;
#pragma unroll
        for (int kk = 0; kk < 4; kk++) {   // each kk: K=32 int8 = 2 chunks
            uint32_t a[4][4];
#pragma unroll
            for (int mt = 0; mt < 4; mt++) {
                int row = warp_m * 64 + mt * 16 + (lane & 15);
                int chunk = kk * 2 + (lane >> 4);
                uint32_t addr = sa + row * 128 + ((chunk * 16) ^ ((row & 7) << 4));
                ldsm4(a[mt][0], a[mt][1], a[mt][2], a[mt][3], addr);
            }
            uint32_t b[2][4];
#pragma unroll
            for (int pair = 0; pair < 2; pair++) {
                int rown = warp_n * 32 + pair * 16 + ((lane >> 4) << 3) + (lane & 7);
                int chunk = kk * 2 + ((lane >> 3) & 1);
                uint32_t addr = sb + rown * 128 + ((chunk * 16) ^ ((rown & 7) << 4));
                ldsm4(b[pair][0], b[pair][1], b[pair][2], b[pair][3], addr);
            }
#pragma unroll
            for (int mt = 0; mt < 4; mt++)
#pragma unroll
                for (int nt = 0; nt < 4; nt++)
                    mma16832_s8(acc[mt][nt], a[mt], &b[nt >> 1][(nt & 1) * 2]);
        }
        __syncthreads();
    }

    // Epilogue stage 1: exp(acc/65536 - 1) -> e4m3 into smem tile (128x128)
    const int lrow = lane >> 2;
    const int lcol = (lane & 3) * 2;
#pragma unroll
    for (int mt = 0; mt < 4; mt++) {
#pragma unroll
        for (int nt = 0; nt < 4; nt++) {
            int r0 = warp_m * 64 + mt * 16 + lrow;
            int cc = warp_n * 32 + nt * 8 + lcol;
            unsigned short p0 = f32x2_to_e4m3x2(
                __expf(__int2float_rn(acc[mt][nt][0]) * ACCSCALE - 1.0f),
                __expf(__int2float_rn(acc[mt][nt][1]) * ACCSCALE - 1.0f));
            unsigned short p1 = f32x2_to_e4m3x2(
                __expf(__int2float_rn(acc[mt][nt][2]) * ACCSCALE - 1.0f),
                __expf(__int2float_rn(acc[mt][nt][3]) * ACCSCALE - 1.0f));
            *reinterpret_cast<unsigned short*>(smem + r0 * 128 + cc) = p0;
            *reinterpret_cast<unsigned short*>(smem + (r0 + 8) * 128 + cc) = p1;
        }
    }
    __syncthreads();

    // Epilogue stage 2: coalesced uint4 stores (64B per thread per pass x 4)
    // 128x128 bytes = 1024 uint4; thread t handles 4 consecutive uint4.
    {
        const uint4* st = reinterpret_cast<const uint4*>(smem);
        int base = tid * 4;             // uint4 index
        int row = base >> 3;            // 8 uint4 per 128B row
        int coloff = (base & 7) * 16;   // byte offset in row
        uint4* gp = reinterpret_cast<uint4*>(
            &g_P0[(size_t)(bi + row) * NN + bj + coloff]);
#pragma unroll
        for (int q = 0; q < 4; q++) gp[q] = st[base + q];
    }
}

// ---------------- fused dual matvec on fp8 P0 (proven 33us shape) ----------
template <bool RECIP>
__global__ __launch_bounds__(256) void dual_matvec_kernel(
    const float* __restrict__ a, const float* __restrict__ b,
    float* __restrict__ out_row, float* __restrict__ out_col) {
    const int ROWS = 64;
    const int tid = threadIdx.x;
    const int j = (blockIdx.x * 256 + tid) * 4;
    const int i0 = blockIdx.y * ROWS;
    __shared__ float bsh[ROWS];
    __shared__ float rowpart[ROWS][9];
    if (tid < ROWS) {
        float v = b[i0 + tid];
        bsh[tid] = RECIP ? 1.0f / v : v;
    }
    __syncthreads();

    float a0 = a[j], a1 = a[j + 1], a2 = a[j + 2], a3 = a[j + 3];
    if (RECIP) {
        a0 = 1.0f / a0; a1 = 1.0f / a1; a2 = 1.0f / a2; a3 = 1.0f / a3;
    }
    float c0 = 0.f, c1 = 0.f, c2 = 0.f, c3 = 0.f;
    const int warp = tid >> 5, lane = tid & 31;
    const uint8_t* base = g_P0 + (size_t)i0 * NN + j;

    for (int ii = 0; ii < ROWS; ii += 2) {
        uint32_t u0 = *reinterpret_cast<const uint32_t*>(base + (size_t)ii * NN);
        uint32_t u1 = *reinterpret_cast<const uint32_t*>(base + (size_t)(ii + 1) * NN);
        float v0[4], v1[4];
        e4m3x4_to_f32(u0, v0);
        e4m3x4_to_f32(u1, v1);
        float b0 = bsh[ii], b1 = bsh[ii + 1];
        c0 = fmaf(v0[0], b0, c0); c1 = fmaf(v0[1], b0, c1);
        c2 = fmaf(v0[2], b0, c2); c3 = fmaf(v0[3], b0, c3);
        c0 = fmaf(v1[0], b1, c0); c1 = fmaf(v1[1], b1, c1);
        c2 = fmaf(v1[2], b1, c2); c3 = fmaf(v1[3], b1, c3);
        float d0 = v0[0] * a0 + v0[1] * a1 + v0[2] * a2 + v0[3] * a3;
        float d1 = v1[0] * a0 + v1[1] * a1 + v1[2] * a2 + v1[3] * a3;
#pragma unroll
        for (int o = 16; o > 0; o >>= 1) {
            d0 += __shfl_down_sync(0xffffffffu, d0, o);
            d1 += __shfl_down_sync(0xffffffffu, d1, o);
        }
        if (lane == 0) {
            rowpart[ii][warp] = d0;
            rowpart[ii + 1][warp] = d1;
        }
    }
    __syncthreads();
    if (tid < ROWS) {
        float sacc = 0.f;
#pragma unroll
        for (int w = 0; w < 8; w++) sacc += rowpart[tid][w];
        atomicAdd(&out_row[i0 + tid], sacc);
    }
    atomicAdd(&out_col[j + 0], c0);
    atomicAdd(&out_col[j + 1], c1);
    atomicAdd(&out_col[j + 2], c2);
    atomicAdd(&out_col[j + 3], c3);
}

// colupd: r = 1/u (persists for CE), c/c2 two-step update from s/s2,
// then zero u,u2,s,s2 for next iteration / CE accumulators.
__global__ void colupd_kernel() {
    int i = blockIdx.x * blockDim.x + threadIdx.x;
    if (i < NN) {
        g_r[i] = 1.0f / g_u[i];
        g_r2[i] = 1.0f / g_u2[i];
        float cv = g_c[i], sv = g_s[i];
        cv *= fmaxf(BD / (cv * sv), 1.0f);
        cv *= fminf(BU / (cv * sv), 1.0f);
        g_c[i] = cv;
        float cv2 = g_c2[i], sv2 = g_s2[i];
        cv2 *= fmaxf(BD / (cv2 * sv2), 1.0f);
        cv2 *= fminf(BU / (cv2 * sv2), 1.0f);
        g_c2[i] = cv2;
        g_u[i] = 0.0f; g_u2[i] = 0.0f;
        g_s[i] = 0.0f; g_s2[i] = 0.0f;
    }
}

// ---------------- fused CE: both directions in ONE read of fp8 P0 ----------
__global__ __launch_bounds__(256) void ce_fused_kernel(const int* __restrict__ labels) {
    const int ROWS = 64;
    const int tid = threadIdx.x;
    const int j = (blockIdx.x * 256 + tid) * 8;
    const int i0 = blockIdx.y * ROWS;
    __shared__ float rsh[ROWS], c2sh[ROWS];
    __shared__ int labsh[ROWS];
    __shared__ float rowpart[ROWS][9];
    if (tid < ROWS) {
        rsh[tid] = g_r[i0 + tid];
        c2sh[tid] = g_c2[i0 + tid];
        labsh[tid] = labels[i0 + tid];
    }
    __syncthreads();

    float cj[8], r2j[8];
    int labc[8];
    {
        float4 t0 = *reinterpret_cast<const float4*>(&g_c[j]);
        float4 t1 = *reinterpret_cast<const float4*>(&g_c[j + 4]);
        cj[0] = t0.x; cj[1] = t0.y; cj[2] = t0.z; cj[3] = t0.w;
        cj[4] = t1.x; cj[5] = t1.y; cj[6] = t1.z; cj[7] = t1.w;
        t0 = *reinterpret_cast<const float4*>(&g_r2[j]);
        t1 = *reinterpret_cast<const float4*>(&g_r2[j + 4]);
        r2j[0] = t0.x; r2j[1] = t0.y; r2j[2] = t0.z; r2j[3] = t0.w;
        r2j[4] = t1.x; r2j[5] = t1.y; r2j[6] = t1.z; r2j[7] = t1.w;
        int4 l0 = *reinterpret_cast<const int4*>(&labels[j]);
        int4 l1 = *reinterpret_cast<const int4*>(&labels[j + 4]);
        labc[0] = l0.x; labc[1] = l0.y; labc[2] = l0.z; labc[3] = l0.w;
        labc[4] = l1.x; labc[5] = l1.y; labc[6] = l1.z; labc[7] = l1.w;
    }
    float colacc[8];
#pragma unroll
    for (int k = 0; k < 8; k++) colacc[k] = 0.0f;
    const int warp = tid >> 5, lane = tid & 31;
    const uint8_t* base = g_P0 + (size_t)i0 * NN + j;

    for (int ii = 0; ii < ROWS; ii++) {
        uint2 u = *reinterpret_cast<const uint2*>(base + (size_t)ii * NN);
        float v[8];
        e4m3x4_to_f32(u.x, v);
        e4m3x4_to_f32(u.y, v + 4);
        const int irow = i0 + ii;
        const float ri = rsh[ii], c2i = c2sh[ii];
        const int labr = labsh[ii];
        float rdot = 0.0f;
#pragma unroll
        for (int k = 0; k < 8; k++) {
            float e1 = ri * v[k] * cj[k];
            float e2 = r2j[k] * v[k] * c2i;
            rdot += __expf(e1);
            colacc[k] += __expf(e2);
            if (j + k == labr) g_diag[irow] = e1;
            if (irow == labc[k]) g_diag2[j + k] = e2;
        }
#pragma unroll
        for (int o = 16; o > 0; o >>= 1)
            rdot += __shfl_down_sync(0xffffffffu, rdot, o);
        if (lane == 0) rowpart[ii][warp] = rdot;
    }
    __syncthreads();
    if (tid < ROWS) {
        float sacc = 0.f;
#pragma unroll
        for (int w = 0; w < 8; w++) sacc += rowpart[tid][w];
        atomicAdd(&g_u[i0 + tid], sacc);
    }
#pragma unroll
    for (int k = 0; k < 8; k++) atomicAdd(&g_u2[j + k], colacc[k]);
}

__global__ __launch_bounds__(256) void ce_reduce_kernel() {
    int t = blockIdx.x * 256 + threadIdx.x;
    float v = (logf(g_u[t]) - g_diag[t]) + (logf(g_u2[t]) - g_diag2[t]);
    __shared__ float wsum[8];
#pragma unroll
    for (int o = 16; o > 0; o >>= 1)
        v += __shfl_down_sync(0xffffffffu, v, o);
    int warp = threadIdx.x >> 5, lane = threadIdx.x & 31;
    if (lane == 0) wsum[warp] = v;
    __syncthreads();
    if (threadIdx.x == 0) {
        float tt = 0.f;
#pragma unroll
        for (int w = 0; w < 8; w++) tt += wsum[w];
        atomicAdd(&g_sums[0], tt);
    }
}

__global__ void finalize_kernel(float* __restrict__ out) {
    out[0] = g_sums[0] / (2.0f * (float)NN);
}

// ---------------- launch ----------------
extern "C" void kernel_launch(void* const* d_in, const int* in_sizes, int n_in,
                              void* d_out, int out_size) {
    const float* A = (const float*)d_in[0];   // all_image_features [N, D]
    const float* B = (const float*)d_in[1];   // all_text_features  [N, D]
    const int* labels = (const int*)d_in[3];
    float* out = (float*)d_out;

    float *c, *c2, *u, *u2, *s, *s2;
    cudaGetSymbolAddress((void**)&c, g_c);
    cudaGetSymbolAddress((void**)&c2, g_c2);
    cudaGetSymbolAddress((void**)&u, g_u);
    cudaGetSymbolAddress((void**)&u2, g_u2);
    cudaGetSymbolAddress((void**)&s, g_s);
    cudaGetSymbolAddress((void**)&s2, g_s2);

    cudaFuncSetAttribute(gemm_i8_exp_kernel,
                         cudaFuncAttributeMaxDynamicSharedMemorySize,
                         2 * STAGE_BYTES);

    init_kernel<<<NN / 256, 256>>>();
    convert_kernel<<<NN * DD / 4 / 256, 256>>>(A, B);
    gemm_i8_exp_kernel<<<dim3(64, 64), 256, 2 * STAGE_BYTES>>>();

    for (int it = 0; it < 5; it++) {
        // pass1: u_i += sum_j P0_ij c_j ; u2_j += sum_i P0_ij c2_i
        dual_matvec_kernel<false><<<dim3(8, 128), 256>>>(c, c2, u, u2);
        // pass2: s2_i += sum_j P0_ij (1/u2_j) ; s_j += sum_i P0_ij (1/u_i)
        dual_matvec_kernel<true><<<dim3(8, 128), 256>>>(u2, u, s2, s);
        colupd_kernel<<<NN / 256, 256>>>();
    }

    ce_fused_kernel<<<dim3(4, 128), 256>>>(labels);
    ce_reduce_kernel<<<NN / 256, 256>>>();
    finalize_kernel<<<1, 1>>>(out);
}